// round 11
// baseline (speedup 1.0000x reference)
#include <cuda_runtime.h>
#include <math.h>

// Problem constants (fixed by the reference)
#define BNUM 64
#define NPER 1024
#define FDIM 128
#define ETOT (BNUM * NPER * 16)   // 1,048,576 edges
#define NT0  (BNUM * NPER)        // 65,536 nodes at layer 1
#define EPG0 16384                // edges per graph, layer 0 (contiguous)
#define ESTR1 16384               // per-graph edge stride after pool1 (HARD bound)
#define ESTR2 16384               // per-graph edge stride after pool2 (HARD bound)
#define CSLOT 64                  // CSR slots per node (in-degree ~Poisson(16))

typedef unsigned long long ull;

// ---------------- scratch (device globals; no runtime allocation) ----------
__device__ float g_P0[(size_t)NT0 * FDIM];      // xW buffer
__device__ float g_P1[(size_t)NT0 * FDIM];      // conv output
__device__ float g_deg[NT0];
__device__ int   g_cnt[NT0];
__device__ float g_score[NT0];
__device__ int   g_perm[NT0];
__device__ float g_vals[NT0];
__device__ int2  g_e2[ETOT];                    // layer-0 edges (src,dst) packed
__device__ float g_ew[ETOT];
__device__ int2  g_e2A[BNUM * ESTR1];           // segmented edges after pool1
__device__ float g_ewA[BNUM * ESTR1];           // (gaps carry weight 0)
__device__ int2  g_e2B[BNUM * ESTR2];           // segmented edges after pool2
__device__ float g_ewB[BNUM * ESTR2];
__device__ __align__(16) int2 g_csr[(size_t)NT0 * CSLOT]; // packed CSR (src, norm)
__device__ float g_pnorm[3];

__device__ __forceinline__ ull fma2(ull a, ull b, ull c) {
    ull d;
    asm("fma.rn.f32x2 %0, %1, %2, %3;" : "=l"(d) : "l"(a), "l"(b), "l"(c));
    return d;
}

// ---------------- k_edges: block = graph -------------------------------------
// pnorm (blocks 0-2) + dtype probe + edge conversion + shared-mem degree +
// layer-1 CSR fill, all fused.
__global__ void __launch_bounds__(1024) k_edges(const int* __restrict__ ei,
                                                const float* __restrict__ ew,
                                                const float* __restrict__ p1,
                                                const float* __restrict__ p2,
                                                const float* __restrict__ p3) {
    __shared__ float sdeg[NPER];
    __shared__ int   scnt[NPER];
    __shared__ int   s64;
    const int g = blockIdx.x, t = threadIdx.x;
    // fused ||p|| for the three pooling layers (blocks 0-2)
    if (g < 3) {
        const float* p = (g == 0) ? p1 : (g == 1) ? p2 : p3;
        if (t < 128) sdeg[t] = p[t] * p[t];
        __syncthreads();
        if (t == 0) {
            float s = 0.f;
            for (int i = 0; i < 128; i++) s += sdeg[i];
            g_pnorm[g] = sqrtf(s);
        }
        __syncthreads();
    }
    sdeg[t] = 0.f;
    scnt[t] = 0;
    if (t == 0) s64 = 1;
    __syncthreads();
    const int e0 = g * EPG0;
    // probe: for int64 edge ids (<2^31) all odd words are 0; for int32 they are
    // node ids (nonzero with overwhelming probability over 512 samples)
    if (t < 512 && ei[2 * (e0 + t) + 1] != 0) s64 = 0;
    __syncthreads();
    const int is64 = s64;
    int   ls[EPG0 / 1024], ld[EPG0 / 1024];
    float lw[EPG0 / 1024];
    #pragma unroll
    for (int j = 0; j < EPG0 / 1024; j++) {
        int e = e0 + t + j * 1024;
        int s, d;
        if (is64) { s = ei[2 * e]; d = ei[2 * (ETOT + e)]; }
        else      { s = ei[e];     d = ei[ETOT + e]; }
        float w = ew[e];
        ls[j] = s; ld[j] = d; lw[j] = w;
        g_e2[e] = make_int2(s, d);
        g_ew[e] = w;
        if (w != 0.f) atomicAdd(&sdeg[d - g * NPER], w);
    }
    __syncthreads();
    #pragma unroll
    for (int j = 0; j < EPG0 / 1024; j++) {
        float w = lw[j];
        if (w == 0.f) continue;
        int s = ls[j], d = ld[j];
        int sl = s - g * NPER, dl = d - g * NPER;
        float nv = rsqrtf(sdeg[sl] + 1.f) * w * rsqrtf(sdeg[dl] + 1.f);
        int pos = atomicAdd(&scnt[dl], 1);
        if (pos < CSLOT) {
            g_csr[(size_t)d * CSLOT + pos] = make_int2(s, __float_as_int(nv));
        }
    }
    __syncthreads();
    g_deg[g * NPER + t] = sdeg[t];
    g_cnt[g * NPER + t] = min(scnt[t], CSLOT);
}

// ---------------- GEMM (f32x2 packed): Y[NT,128] = X[NT,128] @ W[128,128] ----
__global__ void __launch_bounds__(128) k_gemm2(const float* __restrict__ X,
                                               const float* __restrict__ W,
                                               float* __restrict__ Y) {
    __shared__ float2 xs2[32][FDIM];
    const int row0 = blockIdx.x * 32;
    const int tid = threadIdx.x;
    const int tx = tid & 63, ty = tid >> 6;
    #pragma unroll
    for (int i = tid; i < 32 * FDIM; i += 128) {
        int r = i >> 7, k = i & 127;
        float v = X[(row0 + r) * FDIM + k];
        xs2[r][k] = make_float2(v, v);
    }
    __syncthreads();
    const ull* W2 = (const ull*)W;
    ull acc[16];
    #pragma unroll
    for (int r = 0; r < 16; r++) acc[r] = 0ull;
    const ull* xrow = (const ull*)&xs2[ty * 16][0];
    #pragma unroll 4
    for (int k = 0; k < FDIM; k++) {
        ull w2 = W2[k * 64 + tx];
        #pragma unroll
        for (int r = 0; r < 16; r++)
            acc[r] = fma2(xrow[r * FDIM + k], w2, acc[r]);
    }
    float2* Y2 = (float2*)Y;
    #pragma unroll
    for (int r = 0; r < 16; r++) {
        float2 res = *(float2*)&acc[r];
        Y2[(row0 + ty * 16 + r) * 64 + tx] = res;
    }
}

// Same GEMM with fused pool-gather: row m = relu(H[g*n + perm[m]] * vals[m]).
__global__ void __launch_bounds__(128) k_gemm2_g(const float* __restrict__ H,
                                                 const float* __restrict__ W,
                                                 float* __restrict__ Y,
                                                 int n, int kshift) {
    __shared__ float2 xs2[32][FDIM];
    const int row0 = blockIdx.x * 32;
    const int tid = threadIdx.x;
    const int tx = tid & 63, ty = tid >> 6;
    #pragma unroll
    for (int i = tid; i < 32 * FDIM; i += 128) {
        int r = i >> 7, k = i & 127;
        int m = row0 + r;
        int g = m >> kshift;
        int row = g * n + g_perm[m];
        float v = fmaxf(H[row * FDIM + k] * g_vals[m], 0.f);
        xs2[r][k] = make_float2(v, v);
    }
    __syncthreads();
    const ull* W2 = (const ull*)W;
    ull acc[16];
    #pragma unroll
    for (int r = 0; r < 16; r++) acc[r] = 0ull;
    const ull* xrow = (const ull*)&xs2[ty * 16][0];
    #pragma unroll 4
    for (int k = 0; k < FDIM; k++) {
        ull w2 = W2[k * 64 + tx];
        #pragma unroll
        for (int r = 0; r < 16; r++)
            acc[r] = fma2(xrow[r * FDIM + k], w2, acc[r]);
    }
    float2* Y2 = (float2*)Y;
    #pragma unroll
    for (int r = 0; r < 16; r++) {
        float2 res = *(float2*)&acc[r];
        Y2[(row0 + ty * 16 + r) * 64 + tx] = res;
    }
}

// ---------------- aggregate + fused topk score: warp per dst node ------------
__global__ void __launch_bounds__(256, 6) k_aggregate(const float* __restrict__ xW,
                                                      const float* __restrict__ b,
                                                      const float* __restrict__ p,
                                                      float* __restrict__ out,
                                                      int nt, int layer) {
    __shared__ int2 srec[8 * CSLOT];    // 4KB CSR slab for this block's 8 nodes
    const int w = threadIdx.x >> 5;
    const int lane = threadIdx.x & 31;
    const int node = blockIdx.x * 8 + w;
    ((int4*)srec)[threadIdx.x] =
        ((const int4*)(g_csr + (size_t)blockIdx.x * (8 * CSLOT)))[threadIdx.x];
    __syncthreads();
    const float4* xw4 = (const float4*)xW;
    float4 bv = ((const float4*)b)[lane];
    float di = rsqrtf(g_deg[node] + 1.f);
    float sl = di * di;
    float4 sv = xw4[(size_t)node * 32 + lane];
    float4 acc;
    acc.x = sl * sv.x + bv.x;
    acc.y = sl * sv.y + bv.y;
    acc.z = sl * sv.z + bv.z;
    acc.w = sl * sv.w + bv.w;
    const int cnt = g_cnt[node];
    const int2* rec = &srec[w * CSLOT];
    #pragma unroll 4
    for (int j = 0; j < cnt; j++) {
        int2 r0 = rec[j];                          // broadcast LDS.64
        float4 v = xw4[(size_t)r0.x * 32 + lane];  // gathered LDG.128
        float m = __int_as_float(r0.y);
        acc.x = fmaf(m, v.x, acc.x);
        acc.y = fmaf(m, v.y, acc.y);
        acc.z = fmaf(m, v.z, acc.z);
        acc.w = fmaf(m, v.w, acc.w);
    }
    ((float4*)out)[(size_t)node * 32 + lane] = acc;
    // fused topk score
    float4 pv = ((const float4*)p)[lane];
    float ds = acc.x * pv.x + acc.y * pv.y + acc.z * pv.z + acc.w * pv.w;
    #pragma unroll
    for (int o = 16; o > 0; o >>= 1) ds += __shfl_xor_sync(0xffffffffu, ds, o);
    if (lane == 0) {
        float sc = ds / g_pnorm[layer];
        g_score[node] = 1.f / (1.f + expf(-sc));
    }
    (void)nt;
}

// ---------------- topk + remap + segmented compact + deg + CSR fill (+readout)
// block = graph. Hybrid bitonic (register phases j<32). Compaction is
// single-pass and atomic-free: each warp owns a private output segment
// (capacity = its input share) with a register-local running offset; leftover
// gap WEIGHTS are zeroed so every consumer skips gaps via the existing w==0
// check (gap int2 payloads are never dereferenced). Layer 3 runs the fused
// readout instead of the remap phase.
__global__ void k_topk_rf(int n, int k,
                          const int2* __restrict__ e2i, const float* __restrict__ ewi,
                          int istr,
                          int2* __restrict__ e2o, float* __restrict__ ewo,
                          int do_remap,
                          const float* __restrict__ h, const float* __restrict__ Wo,
                          const float* __restrict__ bo, float* __restrict__ out) {
    __shared__ ull   keys[1024];
    __shared__ int   inv[1024];
    __shared__ float sdeg[512];
    __shared__ int   scnt[512];
    __shared__ int   sperm[512];
    __shared__ float svals[512];
    const int g = blockIdx.x, t = threadIdx.x;
    const int lane = t & 31;
    const int w = t >> 5;
    float sc = g_score[g * n + t];
    keys[t] = ((ull)__float_as_uint(sc) << 32) | (unsigned)t;
    inv[t] = -1;
    if (t < k) { sdeg[t] = 0.f; scnt[t] = 0; }
    __syncthreads();
    // hybrid bitonic sort, descending (scores in (0,1): float bits order-preserving)
    for (int ks = 2; ks <= n; ks <<= 1) {
        int j = ks >> 1;
        const bool desc = ((t & ks) == 0);
        for (; j >= 32; j >>= 1) {                 // shared phases
            int ixj = t ^ j;
            if (ixj > t) {
                ull a = keys[t], b2 = keys[ixj];
                if ((a < b2) == desc) { keys[t] = b2; keys[ixj] = a; }
            }
            __syncthreads();
        }
        ull key = keys[t];                         // register phases (j < 32)
        for (; j > 0; j >>= 1) {
            ull other = __shfl_xor_sync(0xffffffffu, key, j);
            bool lower = ((t & j) == 0);
            ull mx = key > other ? key : other;
            ull mn = key > other ? other : key;
            key = (lower == desc) ? mx : mn;
        }
        keys[t] = key;
        __syncthreads();
    }
    if (t < k) {
        ull a = keys[t];
        int idx = (int)(a & 0xffffffffu);
        float val = __uint_as_float((unsigned)(a >> 32));
        g_perm[g * k + t] = idx;
        g_vals[g * k + t] = val;
        sperm[t] = idx;
        svals[t] = val;
        inv[idx] = t;
    }
    __syncthreads();

    if (do_remap) {
        const int ibase = g * istr;
        const int niter = istr / n;
        const int segcap = niter * 32;             // per-warp output capacity
        const int obase = g * istr;                // ostride == istr
        const int wbase = obase + w * segcap;
        int wcount = 0;
        for (int iter = 0; iter < niter; iter++) {
            int i = iter * n + w * 32 + lane;
            int2 sd = e2i[ibase + i];
            float wgt = ewi[ibase + i];
            int slid = -1, dlid = -1;
            if (wgt != 0.f) {                       // guard: gap int2 is garbage
                slid = inv[sd.x - g * n];
                dlid = inv[sd.y - g * n];
            }
            bool valid = (wgt != 0.f) && (slid >= 0) && (dlid >= 0);
            unsigned bal = __ballot_sync(0xffffffffu, valid);
            if (valid) {
                int pos = wbase + wcount + __popc(bal & ((1u << lane) - 1u));
                e2o[pos] = make_int2(g * k + slid, g * k + dlid);
                ewo[pos] = wgt;
                atomicAdd(&sdeg[dlid], wgt);
            }
            wcount += __popc(bal);
        }
        // zero the leftover gap weights in this warp's segment
        for (int i = wbase + wcount + lane; i < wbase + segcap; i += 32)
            ewo[i] = 0.f;
        __syncthreads();
        // CSR fill with fused symmetric norm; gaps skipped via w==0
        for (int i = t; i < istr; i += n) {
            float wgt = ewo[obase + i];
            if (wgt == 0.f) continue;
            int2 sd = e2o[obase + i];
            int slid = sd.x - g * k, dlid = sd.y - g * k;
            float nv = rsqrtf(sdeg[slid] + 1.f) * wgt * rsqrtf(sdeg[dlid] + 1.f);
            int pos = atomicAdd(&scnt[dlid], 1);
            if (pos < CSLOT) {
                g_csr[(size_t)sd.y * CSLOT + pos] = make_int2(sd.x, __float_as_int(nv));
            }
        }
        __syncthreads();
        if (t < k) {
            g_deg[g * k + t] = sdeg[t];
            g_cnt[g * k + t] = min(scnt[t], CSLOT);
        }
    } else {
        // fused readout: gmp||gap over the k kept nodes, then sigmoid(cat@Wo+bo)
        float red_contrib = 0.f;
        if (t < 128) {
            int f = t;
            float mx = -3.0e38f, sm = 0.f;
            for (int nd = 0; nd < k; nd++) {
                int row = g * n + sperm[nd];
                float v = h[row * FDIM + f] * svals[nd];
                v = fmaxf(v, 0.f);
                mx = fmaxf(mx, v);
                sm += v;
            }
            float mean = sm / (float)k;
            out[BNUM + g * 256 + f] = mx;            // cat block: [max | mean]
            out[BNUM + g * 256 + 128 + f] = mean;
            red_contrib = mx * Wo[f] + mean * Wo[128 + f];
        }
        if (t < 128) sdeg[t] = red_contrib;
        __syncthreads();
        for (int s = 64; s > 0; s >>= 1) {
            if (t < s) sdeg[t] += sdeg[t + s];
            __syncthreads();
        }
        if (t == 0) {
            float o = sdeg[0] + bo[0];
            out[g] = 1.f / (1.f + expf(-o));
        }
    }
}

// ---------------- driver -------------------------------------------------------
extern "C" void kernel_launch(void* const* d_in, const int* in_sizes, int n_in,
                              void* d_out, int out_size) {
    const float* x  = (const float*)d_in[0];
    const int*   ei = (const int*)  d_in[1];
    const float* ew = (const float*)d_in[2];
    const float* W1 = (const float*)d_in[4];
    const float* b1 = (const float*)d_in[5];
    const float* p1 = (const float*)d_in[6];
    const float* W2 = (const float*)d_in[7];
    const float* b2 = (const float*)d_in[8];
    const float* p2 = (const float*)d_in[9];
    const float* W3 = (const float*)d_in[10];
    const float* b3 = (const float*)d_in[11];
    const float* p3 = (const float*)d_in[12];
    const float* Wo = (const float*)d_in[13];
    const float* bo = (const float*)d_in[14];
    float* out = (float*)d_out;

    float *P0, *P1;
    cudaGetSymbolAddress((void**)&P0, g_P0);
    cudaGetSymbolAddress((void**)&P1, g_P1);
    int2 *E2, *E2A, *E2B;
    float *EW, *EWA, *EWB;
    cudaGetSymbolAddress((void**)&E2, g_e2);
    cudaGetSymbolAddress((void**)&EW, g_ew);
    cudaGetSymbolAddress((void**)&E2A, g_e2A);
    cudaGetSymbolAddress((void**)&EWA, g_ewA);
    cudaGetSymbolAddress((void**)&E2B, g_e2B);
    cudaGetSymbolAddress((void**)&EWB, g_ewB);

    k_edges<<<BNUM, 1024>>>(ei, ew, p1, p2, p3);

    // ---- layer 1 (n=1024 -> k=512) ----
    k_gemm2<<<NT0 / 32, 128>>>(x, W1, P0);
    k_aggregate<<<NT0 / 8, 256>>>(P0, b1, p1, P1, NT0, 0);
    k_topk_rf<<<BNUM, 1024>>>(1024, 512,
                              E2, EW, EPG0,
                              E2A, EWA, 1,
                              (const float*)nullptr, (const float*)nullptr,
                              (const float*)nullptr, (float*)nullptr);
    // ---- layer 2 (n=512 -> k=256) ----
    k_gemm2_g<<<(BNUM * 512) / 32, 128>>>(P1, W2, P0, 1024, 9);
    k_aggregate<<<(BNUM * 512) / 8, 256>>>(P0, b2, p2, P1, BNUM * 512, 1);
    k_topk_rf<<<BNUM, 512>>>(512, 256,
                             E2A, EWA, ESTR1,
                             E2B, EWB, 1,
                             (const float*)nullptr, (const float*)nullptr,
                             (const float*)nullptr, (float*)nullptr);
    // ---- layer 3 (n=256 -> k=128; sort + fused readout) ----
    k_gemm2_g<<<(BNUM * 256) / 32, 128>>>(P1, W3, P0, 512, 8);
    k_aggregate<<<(BNUM * 256) / 8, 256>>>(P0, b3, p3, P1, BNUM * 256, 2);
    k_topk_rf<<<BNUM, 256>>>(256, 128,
                             E2B, EWB, ESTR2,
                             (int2*)nullptr, (float*)nullptr, 0,
                             P1, Wo, bo, out);

    (void)in_sizes; (void)n_in; (void)out_size;
}

// round 12
// speedup vs baseline: 1.0784x; 1.0784x over previous
#include <cuda_runtime.h>
#include <math.h>

// Problem constants (fixed by the reference)
#define BNUM 64
#define NPER 1024
#define FDIM 128
#define ETOT (BNUM * NPER * 16)   // 1,048,576 edges
#define NT0  (BNUM * NPER)        // 65,536 nodes at layer 1
#define EPG0 16384                // edges per graph, layer 0 (contiguous)
#define ESTR1 16384               // per-graph edge bound after pool1 (HARD bound)
#define ESTR2 16384               // per-graph edge bound after pool2 (HARD bound)
#define CSLOT 64                  // CSR slots per node (in-degree ~Poisson(16))

typedef unsigned long long ull;

// ---------------- scratch (device globals; no runtime allocation) ----------
__device__ float g_P0[(size_t)NT0 * FDIM];      // xW buffer
__device__ float g_P1[(size_t)NT0 * FDIM];      // conv output
__device__ float g_deg[NT0];
__device__ int   g_cnt[NT0];
__device__ float g_score[NT0];
__device__ int   g_perm[NT0];
__device__ float g_vals[NT0];
__device__ int2  g_e2[ETOT];                    // layer-0 edges (src,dst) packed
__device__ float g_ew[ETOT];
__device__ int2  g_e2A[BNUM * ESTR1];           // compacted edges after pool1
__device__ float g_ewA[BNUM * ESTR1];
__device__ int2  g_e2B[BNUM * ESTR2];           // compacted edges after pool2
__device__ float g_ewB[BNUM * ESTR2];
__device__ int   g_gecA[BNUM];                  // per-graph live-edge counts
__device__ int   g_gecB[BNUM];
__device__ __align__(16) int2 g_csr[(size_t)NT0 * CSLOT]; // packed CSR (src, norm)
__device__ float g_pnorm[3];

__device__ __forceinline__ ull fma2(ull a, ull b, ull c) {
    ull d;
    asm("fma.rn.f32x2 %0, %1, %2, %3;" : "=l"(d) : "l"(a), "l"(b), "l"(c));
    return d;
}

// ---------------- k_edges: block = graph -------------------------------------
// pnorm (blocks 0-2) + dtype probe + edge conversion + shared-mem degree +
// layer-1 CSR fill, all fused.
__global__ void __launch_bounds__(1024) k_edges(const int* __restrict__ ei,
                                                const float* __restrict__ ew,
                                                const float* __restrict__ p1,
                                                const float* __restrict__ p2,
                                                const float* __restrict__ p3) {
    __shared__ float sdeg[NPER];
    __shared__ int   scnt[NPER];
    __shared__ int   s64;
    const int g = blockIdx.x, t = threadIdx.x;
    // fused ||p|| for the three pooling layers (blocks 0-2)
    if (g < 3) {
        const float* p = (g == 0) ? p1 : (g == 1) ? p2 : p3;
        if (t < 128) sdeg[t] = p[t] * p[t];
        __syncthreads();
        if (t == 0) {
            float s = 0.f;
            for (int i = 0; i < 128; i++) s += sdeg[i];
            g_pnorm[g] = sqrtf(s);
        }
        __syncthreads();
    }
    sdeg[t] = 0.f;
    scnt[t] = 0;
    if (t == 0) s64 = 1;
    __syncthreads();
    const int e0 = g * EPG0;
    // probe: for int64 edge ids (<2^31) all odd words are 0; for int32 they are
    // node ids (nonzero with overwhelming probability over 512 samples)
    if (t < 512 && ei[2 * (e0 + t) + 1] != 0) s64 = 0;
    __syncthreads();
    const int is64 = s64;
    int   ls[EPG0 / 1024], ld[EPG0 / 1024];
    float lw[EPG0 / 1024];
    #pragma unroll
    for (int j = 0; j < EPG0 / 1024; j++) {
        int e = e0 + t + j * 1024;
        int s, d;
        if (is64) { s = ei[2 * e]; d = ei[2 * (ETOT + e)]; }
        else      { s = ei[e];     d = ei[ETOT + e]; }
        float w = ew[e];
        ls[j] = s; ld[j] = d; lw[j] = w;
        g_e2[e] = make_int2(s, d);
        g_ew[e] = w;
        if (w != 0.f) atomicAdd(&sdeg[d - g * NPER], w);
    }
    __syncthreads();
    #pragma unroll
    for (int j = 0; j < EPG0 / 1024; j++) {
        float w = lw[j];
        if (w == 0.f) continue;
        int s = ls[j], d = ld[j];
        int sl = s - g * NPER, dl = d - g * NPER;
        float nv = rsqrtf(sdeg[sl] + 1.f) * w * rsqrtf(sdeg[dl] + 1.f);
        int pos = atomicAdd(&scnt[dl], 1);
        if (pos < CSLOT) {
            g_csr[(size_t)d * CSLOT + pos] = make_int2(s, __float_as_int(nv));
        }
    }
    __syncthreads();
    g_deg[g * NPER + t] = sdeg[t];
    g_cnt[g * NPER + t] = min(scnt[t], CSLOT);
}

// ---------------- GEMM (f32x2 packed): Y[NT,128] = X[NT,128] @ W[128,128] ----
__global__ void __launch_bounds__(128) k_gemm2(const float* __restrict__ X,
                                               const float* __restrict__ W,
                                               float* __restrict__ Y) {
    __shared__ float2 xs2[32][FDIM];
    const int row0 = blockIdx.x * 32;
    const int tid = threadIdx.x;
    const int tx = tid & 63, ty = tid >> 6;
    #pragma unroll
    for (int i = tid; i < 32 * FDIM; i += 128) {
        int r = i >> 7, k = i & 127;
        float v = X[(row0 + r) * FDIM + k];
        xs2[r][k] = make_float2(v, v);
    }
    __syncthreads();
    const ull* W2 = (const ull*)W;
    ull acc[16];
    #pragma unroll
    for (int r = 0; r < 16; r++) acc[r] = 0ull;
    const ull* xrow = (const ull*)&xs2[ty * 16][0];
    #pragma unroll 4
    for (int k = 0; k < FDIM; k++) {
        ull w2 = W2[k * 64 + tx];
        #pragma unroll
        for (int r = 0; r < 16; r++)
            acc[r] = fma2(xrow[r * FDIM + k], w2, acc[r]);
    }
    float2* Y2 = (float2*)Y;
    #pragma unroll
    for (int r = 0; r < 16; r++) {
        float2 res = *(float2*)&acc[r];
        Y2[(row0 + ty * 16 + r) * 64 + tx] = res;
    }
}

// Same GEMM with fused pool-gather: row m = relu(H[g*n + perm[m]] * vals[m]).
__global__ void __launch_bounds__(128) k_gemm2_g(const float* __restrict__ H,
                                                 const float* __restrict__ W,
                                                 float* __restrict__ Y,
                                                 int n, int kshift) {
    __shared__ float2 xs2[32][FDIM];
    const int row0 = blockIdx.x * 32;
    const int tid = threadIdx.x;
    const int tx = tid & 63, ty = tid >> 6;
    #pragma unroll
    for (int i = tid; i < 32 * FDIM; i += 128) {
        int r = i >> 7, k = i & 127;
        int m = row0 + r;
        int g = m >> kshift;
        int row = g * n + g_perm[m];
        float v = fmaxf(H[row * FDIM + k] * g_vals[m], 0.f);
        xs2[r][k] = make_float2(v, v);
    }
    __syncthreads();
    const ull* W2 = (const ull*)W;
    ull acc[16];
    #pragma unroll
    for (int r = 0; r < 16; r++) acc[r] = 0ull;
    const ull* xrow = (const ull*)&xs2[ty * 16][0];
    #pragma unroll 4
    for (int k = 0; k < FDIM; k++) {
        ull w2 = W2[k * 64 + tx];
        #pragma unroll
        for (int r = 0; r < 16; r++)
            acc[r] = fma2(xrow[r * FDIM + k], w2, acc[r]);
    }
    float2* Y2 = (float2*)Y;
    #pragma unroll
    for (int r = 0; r < 16; r++) {
        float2 res = *(float2*)&acc[r];
        Y2[(row0 + ty * 16 + r) * 64 + tx] = res;
    }
}

// ---------------- aggregate + fused topk score: warp per dst node ------------
__global__ void __launch_bounds__(256, 6) k_aggregate(const float* __restrict__ xW,
                                                      const float* __restrict__ b,
                                                      const float* __restrict__ p,
                                                      float* __restrict__ out,
                                                      int nt, int layer) {
    __shared__ int2 srec[8 * CSLOT];    // 4KB CSR slab for this block's 8 nodes
    const int w = threadIdx.x >> 5;
    const int lane = threadIdx.x & 31;
    const int node = blockIdx.x * 8 + w;
    ((int4*)srec)[threadIdx.x] =
        ((const int4*)(g_csr + (size_t)blockIdx.x * (8 * CSLOT)))[threadIdx.x];
    __syncthreads();
    const float4* xw4 = (const float4*)xW;
    float4 bv = ((const float4*)b)[lane];
    float di = rsqrtf(g_deg[node] + 1.f);
    float sl = di * di;
    float4 sv = xw4[(size_t)node * 32 + lane];
    float4 acc;
    acc.x = sl * sv.x + bv.x;
    acc.y = sl * sv.y + bv.y;
    acc.z = sl * sv.z + bv.z;
    acc.w = sl * sv.w + bv.w;
    const int cnt = g_cnt[node];
    const int2* rec = &srec[w * CSLOT];
    #pragma unroll 4
    for (int j = 0; j < cnt; j++) {
        int2 r0 = rec[j];                          // broadcast LDS.64
        float4 v = xw4[(size_t)r0.x * 32 + lane];  // gathered LDG.128
        float m = __int_as_float(r0.y);
        acc.x = fmaf(m, v.x, acc.x);
        acc.y = fmaf(m, v.y, acc.y);
        acc.z = fmaf(m, v.z, acc.z);
        acc.w = fmaf(m, v.w, acc.w);
    }
    ((float4*)out)[(size_t)node * 32 + lane] = acc;
    // fused topk score
    float4 pv = ((const float4*)p)[lane];
    float ds = acc.x * pv.x + acc.y * pv.y + acc.z * pv.z + acc.w * pv.w;
    #pragma unroll
    for (int o = 16; o > 0; o >>= 1) ds += __shfl_xor_sync(0xffffffffu, ds, o);
    if (lane == 0) {
        float sc = ds / g_pnorm[layer];
        g_score[node] = 1.f / (1.f + expf(-sc));
    }
    (void)nt;
}

// ---------------- topk + remap + compact + deg + CSR fill (+readout) ---------
// block = graph. Hybrid bitonic (register phases for j<32) + the round-9
// warp-aggregated DENSE compaction (1 shared atomic per warp-iteration).
// Layer 3 runs the fused readout instead of the remap phase.
__global__ void k_topk_rf(int n, int k,
                          const int2* __restrict__ e2i, const float* __restrict__ ewi,
                          int istride, const int* __restrict__ gcin, int fixedc,
                          int2* __restrict__ e2o, float* __restrict__ ewo,
                          int ostride, int* __restrict__ gcout, int do_remap,
                          const float* __restrict__ h, const float* __restrict__ Wo,
                          const float* __restrict__ bo, float* __restrict__ out) {
    __shared__ ull   keys[1024];
    __shared__ int   inv[1024];
    __shared__ float sdeg[512];
    __shared__ int   scnt[512];
    __shared__ int   sperm[512];
    __shared__ float svals[512];
    __shared__ int   secnt;
    const int g = blockIdx.x, t = threadIdx.x;
    const int lane = t & 31;
    float sc = g_score[g * n + t];
    keys[t] = ((ull)__float_as_uint(sc) << 32) | (unsigned)t;
    inv[t] = -1;
    if (t < k) { sdeg[t] = 0.f; scnt[t] = 0; }
    if (t == 0) secnt = 0;
    __syncthreads();
    // hybrid bitonic sort, descending (scores in (0,1): float bits order-preserving)
    for (int ks = 2; ks <= n; ks <<= 1) {
        int j = ks >> 1;
        const bool desc = ((t & ks) == 0);
        for (; j >= 32; j >>= 1) {                 // shared phases
            int ixj = t ^ j;
            if (ixj > t) {
                ull a = keys[t], b2 = keys[ixj];
                if ((a < b2) == desc) { keys[t] = b2; keys[ixj] = a; }
            }
            __syncthreads();
        }
        ull key = keys[t];                         // register phases (j < 32)
        for (; j > 0; j >>= 1) {
            ull other = __shfl_xor_sync(0xffffffffu, key, j);
            bool lower = ((t & j) == 0);
            ull mx = key > other ? key : other;
            ull mn = key > other ? other : key;
            key = (lower == desc) ? mx : mn;
        }
        keys[t] = key;
        __syncthreads();
    }
    if (t < k) {
        ull a = keys[t];
        int idx = (int)(a & 0xffffffffu);
        float val = __uint_as_float((unsigned)(a >> 32));
        g_perm[g * k + t] = idx;
        g_vals[g * k + t] = val;
        sperm[t] = idx;
        svals[t] = val;
        inv[idx] = t;
    }
    __syncthreads();

    if (do_remap) {
        const int cin = fixedc ? fixedc : gcin[g];
        const int ibase = g * istride;
        const int obase = g * ostride;
        // warp-aggregated DENSE compaction: one shared atomic per warp, popc prefix
        for (int i0 = (t & ~31); i0 < cin; i0 += n) {
            int i = i0 + lane;
            int slid = -1, dlid = -1;
            float w = 0.f;
            bool valid = false;
            if (i < cin) {
                int2 sd = e2i[ibase + i];
                w = ewi[ibase + i];
                slid = inv[sd.x - g * n]; dlid = inv[sd.y - g * n];
                valid = (w != 0.f) && (slid >= 0) && (dlid >= 0);
            }
            unsigned bal = __ballot_sync(0xffffffffu, valid);
            int cntb = __popc(bal);
            int base = 0;
            if (lane == 0 && cntb) base = atomicAdd(&secnt, cntb);
            base = __shfl_sync(0xffffffffu, base, 0);
            if (valid) {
                int pos = base + __popc(bal & ((1u << lane) - 1u));
                if (pos < ostride) {
                    e2o[obase + pos] = make_int2(g * k + slid, g * k + dlid);
                    ewo[obase + pos] = w;
                    atomicAdd(&sdeg[dlid], w);
                }
            }
        }
        __syncthreads();
        int cout = min(secnt, ostride);
        if (t == 0) gcout[g] = cout;
        // CSR fill with fused symmetric norm (packed int2 record, single STG.64)
        for (int i = t; i < cout; i += n) {
            int2 sd = e2o[obase + i];
            float w = ewo[obase + i];
            int slid = sd.x - g * k, dlid = sd.y - g * k;
            float nv = rsqrtf(sdeg[slid] + 1.f) * w * rsqrtf(sdeg[dlid] + 1.f);
            int pos = atomicAdd(&scnt[dlid], 1);
            if (pos < CSLOT) {
                g_csr[(size_t)sd.y * CSLOT + pos] = make_int2(sd.x, __float_as_int(nv));
            }
        }
        __syncthreads();
        if (t < k) {
            g_deg[g * k + t] = sdeg[t];
            g_cnt[g * k + t] = min(scnt[t], CSLOT);
        }
    } else {
        // fused readout: gmp||gap over the k kept nodes, then sigmoid(cat@Wo+bo)
        float red_contrib = 0.f;
        if (t < 128) {
            int f = t;
            float mx = -3.0e38f, sm = 0.f;
            for (int nd = 0; nd < k; nd++) {
                int row = g * n + sperm[nd];
                float v = h[row * FDIM + f] * svals[nd];
                v = fmaxf(v, 0.f);
                mx = fmaxf(mx, v);
                sm += v;
            }
            float mean = sm / (float)k;
            out[BNUM + g * 256 + f] = mx;            // cat block: [max | mean]
            out[BNUM + g * 256 + 128 + f] = mean;
            red_contrib = mx * Wo[f] + mean * Wo[128 + f];
        }
        if (t < 128) sdeg[t] = red_contrib;
        __syncthreads();
        for (int s = 64; s > 0; s >>= 1) {
            if (t < s) sdeg[t] += sdeg[t + s];
            __syncthreads();
        }
        if (t == 0) {
            float o = sdeg[0] + bo[0];
            out[g] = 1.f / (1.f + expf(-o));
        }
    }
}

// ---------------- driver -------------------------------------------------------
extern "C" void kernel_launch(void* const* d_in, const int* in_sizes, int n_in,
                              void* d_out, int out_size) {
    const float* x  = (const float*)d_in[0];
    const int*   ei = (const int*)  d_in[1];
    const float* ew = (const float*)d_in[2];
    const float* W1 = (const float*)d_in[4];
    const float* b1 = (const float*)d_in[5];
    const float* p1 = (const float*)d_in[6];
    const float* W2 = (const float*)d_in[7];
    const float* b2 = (const float*)d_in[8];
    const float* p2 = (const float*)d_in[9];
    const float* W3 = (const float*)d_in[10];
    const float* b3 = (const float*)d_in[11];
    const float* p3 = (const float*)d_in[12];
    const float* Wo = (const float*)d_in[13];
    const float* bo = (const float*)d_in[14];
    float* out = (float*)d_out;

    float *P0, *P1;
    cudaGetSymbolAddress((void**)&P0, g_P0);
    cudaGetSymbolAddress((void**)&P1, g_P1);
    int2 *E2, *E2A, *E2B;
    int *GCA, *GCB;
    float *EW, *EWA, *EWB;
    cudaGetSymbolAddress((void**)&E2, g_e2);
    cudaGetSymbolAddress((void**)&EW, g_ew);
    cudaGetSymbolAddress((void**)&E2A, g_e2A);
    cudaGetSymbolAddress((void**)&EWA, g_ewA);
    cudaGetSymbolAddress((void**)&E2B, g_e2B);
    cudaGetSymbolAddress((void**)&EWB, g_ewB);
    cudaGetSymbolAddress((void**)&GCA, g_gecA);
    cudaGetSymbolAddress((void**)&GCB, g_gecB);

    k_edges<<<BNUM, 1024>>>(ei, ew, p1, p2, p3);

    // ---- layer 1 (n=1024 -> k=512) ----
    k_gemm2<<<NT0 / 32, 128>>>(x, W1, P0);
    k_aggregate<<<NT0 / 8, 256>>>(P0, b1, p1, P1, NT0, 0);
    k_topk_rf<<<BNUM, 1024>>>(1024, 512,
                              E2, EW, EPG0, (const int*)nullptr, EPG0,
                              E2A, EWA, ESTR1, GCA, 1,
                              (const float*)nullptr, (const float*)nullptr,
                              (const float*)nullptr, (float*)nullptr);
    // ---- layer 2 (n=512 -> k=256) ----
    k_gemm2_g<<<(BNUM * 512) / 32, 128>>>(P1, W2, P0, 1024, 9);
    k_aggregate<<<(BNUM * 512) / 8, 256>>>(P0, b2, p2, P1, BNUM * 512, 1);
    k_topk_rf<<<BNUM, 512>>>(512, 256,
                             E2A, EWA, ESTR1, GCA, 0,
                             E2B, EWB, ESTR2, GCB, 1,
                             (const float*)nullptr, (const float*)nullptr,
                             (const float*)nullptr, (float*)nullptr);
    // ---- layer 3 (n=256 -> k=128; sort + fused readout) ----
    k_gemm2_g<<<(BNUM * 256) / 32, 128>>>(P1, W3, P0, 512, 8);
    k_aggregate<<<(BNUM * 256) / 8, 256>>>(P0, b3, p3, P1, BNUM * 256, 2);
    k_topk_rf<<<BNUM, 256>>>(256, 128,
                             E2B, EWB, ESTR2, GCB, 0,
                             (int2*)nullptr, (float*)nullptr, 0,
                             (int*)nullptr, 0,
                             P1, Wo, bo, out);

    (void)in_sizes; (void)n_in; (void)out_size;
}

// round 14
// speedup vs baseline: 1.0882x; 1.0091x over previous
#include <cuda_runtime.h>
#include <math.h>

// Problem constants (fixed by the reference)
#define BNUM 64
#define NPER 1024
#define FDIM 128
#define ETOT (BNUM * NPER * 16)   // 1,048,576 edges
#define NT0  (BNUM * NPER)        // 65,536 nodes at layer 1
#define EPG0 16384                // edges per graph, layer 0 (contiguous)
#define ESTR1 16384               // per-graph edge bound after pool1 (HARD bound)
#define ESTR2 16384               // per-graph edge bound after pool2 (HARD bound)
#define CSLOT 64                  // CSR slots per node (in-degree ~Poisson(16))

typedef unsigned long long ull;

// ---------------- scratch (device globals; no runtime allocation) ----------
__device__ float g_P0[(size_t)NT0 * FDIM];      // xW buffer
__device__ float g_P1[(size_t)NT0 * FDIM];      // conv output
__device__ float g_deg[NT0];
__device__ int   g_cnt[NT0];
__device__ float g_score[NT0];
__device__ int   g_perm[NT0];
__device__ float g_vals[NT0];
__device__ int2  g_e2[ETOT];                    // layer-0 edges (src,dst) packed
__device__ float g_ew[ETOT];
__device__ int2  g_e2A[BNUM * ESTR1];           // compacted edges after pool1
__device__ float g_ewA[BNUM * ESTR1];
__device__ int2  g_e2B[BNUM * ESTR2];           // compacted edges after pool2
__device__ float g_ewB[BNUM * ESTR2];
__device__ int   g_gecA[BNUM];                  // per-graph live-edge counts
__device__ int   g_gecB[BNUM];
__device__ __align__(16) int2 g_csr[(size_t)NT0 * CSLOT]; // packed CSR (src, norm)
__device__ float g_pnorm[3];

__device__ __forceinline__ ull fma2(ull a, ull b, ull c) {
    ull d;
    asm("fma.rn.f32x2 %0, %1, %2, %3;" : "=l"(d) : "l"(a), "l"(b), "l"(c));
    return d;
}

// ---------------- k_edges: block = graph -------------------------------------
// pnorm (blocks 0-2) + dtype probe + edge conversion + shared-mem degree +
// layer-1 CSR fill, all fused.
__global__ void __launch_bounds__(1024) k_edges(const int* __restrict__ ei,
                                                const float* __restrict__ ew,
                                                const float* __restrict__ p1,
                                                const float* __restrict__ p2,
                                                const float* __restrict__ p3) {
    __shared__ float sdeg[NPER];
    __shared__ int   scnt[NPER];
    __shared__ int   s64;
    const int g = blockIdx.x, t = threadIdx.x;
    // fused ||p|| for the three pooling layers (blocks 0-2)
    if (g < 3) {
        const float* p = (g == 0) ? p1 : (g == 1) ? p2 : p3;
        if (t < 128) sdeg[t] = p[t] * p[t];
        __syncthreads();
        if (t == 0) {
            float s = 0.f;
            for (int i = 0; i < 128; i++) s += sdeg[i];
            g_pnorm[g] = sqrtf(s);
        }
        __syncthreads();
    }
    sdeg[t] = 0.f;
    scnt[t] = 0;
    if (t == 0) s64 = 1;
    __syncthreads();
    const int e0 = g * EPG0;
    // probe: for int64 edge ids (<2^31) all odd words are 0; for int32 they are
    // node ids (nonzero with overwhelming probability over 512 samples)
    if (t < 512 && ei[2 * (e0 + t) + 1] != 0) s64 = 0;
    __syncthreads();
    const int is64 = s64;
    int   ls[EPG0 / 1024], ld[EPG0 / 1024];
    float lw[EPG0 / 1024];
    #pragma unroll
    for (int j = 0; j < EPG0 / 1024; j++) {
        int e = e0 + t + j * 1024;
        int s, d;
        if (is64) { s = ei[2 * e]; d = ei[2 * (ETOT + e)]; }
        else      { s = ei[e];     d = ei[ETOT + e]; }
        float w = ew[e];
        ls[j] = s; ld[j] = d; lw[j] = w;
        g_e2[e] = make_int2(s, d);
        g_ew[e] = w;
        if (w != 0.f) atomicAdd(&sdeg[d - g * NPER], w);
    }
    __syncthreads();
    #pragma unroll
    for (int j = 0; j < EPG0 / 1024; j++) {
        float w = lw[j];
        if (w == 0.f) continue;
        int s = ls[j], d = ld[j];
        int sl = s - g * NPER, dl = d - g * NPER;
        float nv = rsqrtf(sdeg[sl] + 1.f) * w * rsqrtf(sdeg[dl] + 1.f);
        int pos = atomicAdd(&scnt[dl], 1);
        if (pos < CSLOT) {
            g_csr[(size_t)d * CSLOT + pos] = make_int2(s, __float_as_int(nv));
        }
    }
    __syncthreads();
    g_deg[g * NPER + t] = sdeg[t];
    g_cnt[g * NPER + t] = min(scnt[t], CSLOT);
}

// ---------------- GEMM (f32x2 packed): Y[NT,128] = X[NT,128] @ W[128,128] ----
__global__ void __launch_bounds__(128) k_gemm2(const float* __restrict__ X,
                                               const float* __restrict__ W,
                                               float* __restrict__ Y) {
    __shared__ float2 xs2[32][FDIM];
    const int row0 = blockIdx.x * 32;
    const int tid = threadIdx.x;
    const int tx = tid & 63, ty = tid >> 6;
    #pragma unroll
    for (int i = tid; i < 32 * FDIM; i += 128) {
        int r = i >> 7, k = i & 127;
        float v = X[(row0 + r) * FDIM + k];
        xs2[r][k] = make_float2(v, v);
    }
    __syncthreads();
    const ull* W2 = (const ull*)W;
    ull acc[16];
    #pragma unroll
    for (int r = 0; r < 16; r++) acc[r] = 0ull;
    const ull* xrow = (const ull*)&xs2[ty * 16][0];
    #pragma unroll 4
    for (int k = 0; k < FDIM; k++) {
        ull w2 = W2[k * 64 + tx];
        #pragma unroll
        for (int r = 0; r < 16; r++)
            acc[r] = fma2(xrow[r * FDIM + k], w2, acc[r]);
    }
    float2* Y2 = (float2*)Y;
    #pragma unroll
    for (int r = 0; r < 16; r++) {
        float2 res = *(float2*)&acc[r];
        Y2[(row0 + ty * 16 + r) * 64 + tx] = res;
    }
}

// Same GEMM with fused pool-gather: row m = relu(H[g*n + perm[m]] * vals[m]).
__global__ void __launch_bounds__(128) k_gemm2_g(const float* __restrict__ H,
                                                 const float* __restrict__ W,
                                                 float* __restrict__ Y,
                                                 int n, int kshift) {
    __shared__ float2 xs2[32][FDIM];
    const int row0 = blockIdx.x * 32;
    const int tid = threadIdx.x;
    const int tx = tid & 63, ty = tid >> 6;
    #pragma unroll
    for (int i = tid; i < 32 * FDIM; i += 128) {
        int r = i >> 7, k = i & 127;
        int m = row0 + r;
        int g = m >> kshift;
        int row = g * n + g_perm[m];
        float v = fmaxf(H[row * FDIM + k] * g_vals[m], 0.f);
        xs2[r][k] = make_float2(v, v);
    }
    __syncthreads();
    const ull* W2 = (const ull*)W;
    ull acc[16];
    #pragma unroll
    for (int r = 0; r < 16; r++) acc[r] = 0ull;
    const ull* xrow = (const ull*)&xs2[ty * 16][0];
    #pragma unroll 4
    for (int k = 0; k < FDIM; k++) {
        ull w2 = W2[k * 64 + tx];
        #pragma unroll
        for (int r = 0; r < 16; r++)
            acc[r] = fma2(xrow[r * FDIM + k], w2, acc[r]);
    }
    float2* Y2 = (float2*)Y;
    #pragma unroll
    for (int r = 0; r < 16; r++) {
        float2 res = *(float2*)&acc[r];
        Y2[(row0 + ty * 16 + r) * 64 + tx] = res;
    }
}

// ---------------- aggregate + fused topk score: warp per dst node ------------
// minBlocks=7 caps regs (~36) for 56-warp theoretical occupancy; this kernel
// is latency-bound and occupancy is the hiding mechanism.
__global__ void __launch_bounds__(256, 7) k_aggregate(const float* __restrict__ xW,
                                                      const float* __restrict__ b,
                                                      const float* __restrict__ p,
                                                      float* __restrict__ out,
                                                      int nt, int layer) {
    __shared__ int2 srec[8 * CSLOT];    // 4KB CSR slab for this block's 8 nodes
    const int w = threadIdx.x >> 5;
    const int lane = threadIdx.x & 31;
    const int node = blockIdx.x * 8 + w;
    ((int4*)srec)[threadIdx.x] =
        ((const int4*)(g_csr + (size_t)blockIdx.x * (8 * CSLOT)))[threadIdx.x];
    __syncthreads();
    const float4* xw4 = (const float4*)xW;
    float4 bv = ((const float4*)b)[lane];
    float di = rsqrtf(g_deg[node] + 1.f);
    float sl = di * di;
    float4 sv = xw4[(size_t)node * 32 + lane];
    float4 acc;
    acc.x = sl * sv.x + bv.x;
    acc.y = sl * sv.y + bv.y;
    acc.z = sl * sv.z + bv.z;
    acc.w = sl * sv.w + bv.w;
    const int cnt = g_cnt[node];
    const int2* rec = &srec[w * CSLOT];
    #pragma unroll 4
    for (int j = 0; j < cnt; j++) {
        int2 r0 = rec[j];                          // broadcast LDS.64
        float4 v = xw4[(size_t)r0.x * 32 + lane];  // gathered LDG.128
        float m = __int_as_float(r0.y);
        acc.x = fmaf(m, v.x, acc.x);
        acc.y = fmaf(m, v.y, acc.y);
        acc.z = fmaf(m, v.z, acc.z);
        acc.w = fmaf(m, v.w, acc.w);
    }
    ((float4*)out)[(size_t)node * 32 + lane] = acc;
    // fused topk score
    float4 pv = ((const float4*)p)[lane];
    float ds = acc.x * pv.x + acc.y * pv.y + acc.z * pv.z + acc.w * pv.w;
    #pragma unroll
    for (int o = 16; o > 0; o >>= 1) ds += __shfl_xor_sync(0xffffffffu, ds, o);
    if (lane == 0) {
        float sc = ds / g_pnorm[layer];
        g_score[node] = 1.f / (1.f + expf(-sc));
    }
    (void)nt;
}

// ---------------- topk + remap + compact + deg + CSR fill (+readout) ---------
// block = graph. 64-bit exact sort keys (score bits : idx) — NEVER quantize
// the selection key (round-13 lesson). Hybrid bitonic (register phases for
// j<32) + warp-aggregated DENSE compaction. Layer 3 runs the fused readout.
__global__ void k_topk_rf(int n, int k,
                          const int2* __restrict__ e2i, const float* __restrict__ ewi,
                          int istride, const int* __restrict__ gcin, int fixedc,
                          int2* __restrict__ e2o, float* __restrict__ ewo,
                          int ostride, int* __restrict__ gcout, int do_remap,
                          const float* __restrict__ h, const float* __restrict__ Wo,
                          const float* __restrict__ bo, float* __restrict__ out) {
    __shared__ ull   keys[1024];
    __shared__ int   inv[1024];
    __shared__ float sdeg[512];
    __shared__ int   scnt[512];
    __shared__ int   sperm[512];
    __shared__ float svals[512];
    __shared__ int   secnt;
    const int g = blockIdx.x, t = threadIdx.x;
    const int lane = t & 31;
    float sc = g_score[g * n + t];
    keys[t] = ((ull)__float_as_uint(sc) << 32) | (unsigned)t;
    inv[t] = -1;
    if (t < k) { sdeg[t] = 0.f; scnt[t] = 0; }
    if (t == 0) secnt = 0;
    __syncthreads();
    // hybrid bitonic sort, descending (scores in (0,1): float bits order-preserving)
    for (int ks = 2; ks <= n; ks <<= 1) {
        int j = ks >> 1;
        const bool desc = ((t & ks) == 0);
        for (; j >= 32; j >>= 1) {                 // shared phases
            int ixj = t ^ j;
            if (ixj > t) {
                ull a = keys[t], b2 = keys[ixj];
                if ((a < b2) == desc) { keys[t] = b2; keys[ixj] = a; }
            }
            __syncthreads();
        }
        ull key = keys[t];                         // register phases (j < 32)
        for (; j > 0; j >>= 1) {
            ull other = __shfl_xor_sync(0xffffffffu, key, j);
            bool lower = ((t & j) == 0);
            ull mx = key > other ? key : other;
            ull mn = key > other ? other : key;
            key = (lower == desc) ? mx : mn;
        }
        keys[t] = key;
        __syncthreads();
    }
    if (t < k) {
        ull a = keys[t];
        int idx = (int)(a & 0xffffffffu);
        float val = __uint_as_float((unsigned)(a >> 32));
        g_perm[g * k + t] = idx;
        g_vals[g * k + t] = val;
        sperm[t] = idx;
        svals[t] = val;
        inv[idx] = t;
    }
    __syncthreads();

    if (do_remap) {
        const int cin = fixedc ? fixedc : gcin[g];
        const int ibase = g * istride;
        const int obase = g * ostride;
        // warp-aggregated DENSE compaction: one shared atomic per warp, popc prefix
        for (int i0 = (t & ~31); i0 < cin; i0 += n) {
            int i = i0 + lane;
            int slid = -1, dlid = -1;
            float w = 0.f;
            bool valid = false;
            if (i < cin) {
                int2 sd = e2i[ibase + i];
                w = ewi[ibase + i];
                slid = inv[sd.x - g * n]; dlid = inv[sd.y - g * n];
                valid = (w != 0.f) && (slid >= 0) && (dlid >= 0);
            }
            unsigned bal = __ballot_sync(0xffffffffu, valid);
            int cntb = __popc(bal);
            int base = 0;
            if (lane == 0 && cntb) base = atomicAdd(&secnt, cntb);
            base = __shfl_sync(0xffffffffu, base, 0);
            if (valid) {
                int pos = base + __popc(bal & ((1u << lane) - 1u));
                if (pos < ostride) {
                    e2o[obase + pos] = make_int2(g * k + slid, g * k + dlid);
                    ewo[obase + pos] = w;
                    atomicAdd(&sdeg[dlid], w);
                }
            }
        }
        __syncthreads();
        int cout = min(secnt, ostride);
        if (t == 0) gcout[g] = cout;
        // CSR fill with fused symmetric norm (packed int2 record, single STG.64)
        for (int i = t; i < cout; i += n) {
            int2 sd = e2o[obase + i];
            float w = ewo[obase + i];
            int slid = sd.x - g * k, dlid = sd.y - g * k;
            float nv = rsqrtf(sdeg[slid] + 1.f) * w * rsqrtf(sdeg[dlid] + 1.f);
            int pos = atomicAdd(&scnt[dlid], 1);
            if (pos < CSLOT) {
                g_csr[(size_t)sd.y * CSLOT + pos] = make_int2(sd.x, __float_as_int(nv));
            }
        }
        __syncthreads();
        if (t < k) {
            g_deg[g * k + t] = sdeg[t];
            g_cnt[g * k + t] = min(scnt[t], CSLOT);
        }
    } else {
        // fused readout: gmp||gap over the k kept nodes, then sigmoid(cat@Wo+bo)
        float red_contrib = 0.f;
        if (t < 128) {
            int f = t;
            float mx = -3.0e38f, sm = 0.f;
            for (int nd = 0; nd < k; nd++) {
                int row = g * n + sperm[nd];
                float v = h[row * FDIM + f] * svals[nd];
                v = fmaxf(v, 0.f);
                mx = fmaxf(mx, v);
                sm += v;
            }
            float mean = sm / (float)k;
            out[BNUM + g * 256 + f] = mx;            // cat block: [max | mean]
            out[BNUM + g * 256 + 128 + f] = mean;
            red_contrib = mx * Wo[f] + mean * Wo[128 + f];
        }
        if (t < 128) sdeg[t] = red_contrib;
        __syncthreads();
        for (int s = 64; s > 0; s >>= 1) {
            if (t < s) sdeg[t] += sdeg[t + s];
            __syncthreads();
        }
        if (t == 0) {
            float o = sdeg[0] + bo[0];
            out[g] = 1.f / (1.f + expf(-o));
        }
    }
}

// ---------------- driver -------------------------------------------------------
extern "C" void kernel_launch(void* const* d_in, const int* in_sizes, int n_in,
                              void* d_out, int out_size) {
    const float* x  = (const float*)d_in[0];
    const int*   ei = (const int*)  d_in[1];
    const float* ew = (const float*)d_in[2];
    const float* W1 = (const float*)d_in[4];
    const float* b1 = (const float*)d_in[5];
    const float* p1 = (const float*)d_in[6];
    const float* W2 = (const float*)d_in[7];
    const float* b2 = (const float*)d_in[8];
    const float* p2 = (const float*)d_in[9];
    const float* W3 = (const float*)d_in[10];
    const float* b3 = (const float*)d_in[11];
    const float* p3 = (const float*)d_in[12];
    const float* Wo = (const float*)d_in[13];
    const float* bo = (const float*)d_in[14];
    float* out = (float*)d_out;

    float *P0, *P1;
    cudaGetSymbolAddress((void**)&P0, g_P0);
    cudaGetSymbolAddress((void**)&P1, g_P1);
    int2 *E2, *E2A, *E2B;
    int *GCA, *GCB;
    float *EW, *EWA, *EWB;
    cudaGetSymbolAddress((void**)&E2, g_e2);
    cudaGetSymbolAddress((void**)&EW, g_ew);
    cudaGetSymbolAddress((void**)&E2A, g_e2A);
    cudaGetSymbolAddress((void**)&EWA, g_ewA);
    cudaGetSymbolAddress((void**)&E2B, g_e2B);
    cudaGetSymbolAddress((void**)&EWB, g_ewB);
    cudaGetSymbolAddress((void**)&GCA, g_gecA);
    cudaGetSymbolAddress((void**)&GCB, g_gecB);

    k_edges<<<BNUM, 1024>>>(ei, ew, p1, p2, p3);

    // ---- layer 1 (n=1024 -> k=512) ----
    k_gemm2<<<NT0 / 32, 128>>>(x, W1, P0);
    k_aggregate<<<NT0 / 8, 256>>>(P0, b1, p1, P1, NT0, 0);
    k_topk_rf<<<BNUM, 1024>>>(1024, 512,
                              E2, EW, EPG0, (const int*)nullptr, EPG0,
                              E2A, EWA, ESTR1, GCA, 1,
                              (const float*)nullptr, (const float*)nullptr,
                              (const float*)nullptr, (float*)nullptr);
    // ---- layer 2 (n=512 -> k=256) ----
    k_gemm2_g<<<(BNUM * 512) / 32, 128>>>(P1, W2, P0, 1024, 9);
    k_aggregate<<<(BNUM * 512) / 8, 256>>>(P0, b2, p2, P1, BNUM * 512, 1);
    k_topk_rf<<<BNUM, 512>>>(512, 256,
                             E2A, EWA, ESTR1, GCA, 0,
                             E2B, EWB, ESTR2, GCB, 1,
                             (const float*)nullptr, (const float*)nullptr,
                             (const float*)nullptr, (float*)nullptr);
    // ---- layer 3 (n=256 -> k=128; sort + fused readout) ----
    k_gemm2_g<<<(BNUM * 256) / 32, 128>>>(P1, W3, P0, 512, 8);
    k_aggregate<<<(BNUM * 256) / 8, 256>>>(P0, b3, p3, P1, BNUM * 256, 2);
    k_topk_rf<<<BNUM, 256>>>(256, 128,
                             E2B, EWB, ESTR2, GCB, 0,
                             (int2*)nullptr, (float*)nullptr, 0,
                             (int*)nullptr, 0,
                             P1, Wo, bo, out);

    (void)in_sizes; (void)n_in; (void)out_size;
}